// round 15
// baseline (speedup 1.0000x reference)
#include <cuda_runtime.h>
#include <cuda_fp16.h>
#include <math.h>
#include <stdint.h>

// Problem constants
#define BH    32
#define NSEQ  4096
#define DD    128
#define FF    256
#define NTOK  (BH*NSEQ)
#define KSPLIT 4

// Scratch (device globals: allocation-free rule)
__device__ uint4  g_phiqf[(size_t)(NTOK/16)*16*32];  // phi_q in A-fragment order
__device__ __half g_phi_k[(size_t)NTOK*FF];
__device__ float  g_kvp[(size_t)KSPLIT*BH*FF*DD];
__device__ float  g_ksp[(size_t)KSPLIT*BH*FF];
__device__ __half g_kvh[(size_t)BH*FF*DD];
__device__ float  g_ksum[(size_t)BH*FF];
__device__ uint4  g_Wf[12288];            // W in mma B-fragment order

// ---------------------------------------------------------------------------
// helpers
// ---------------------------------------------------------------------------
__device__ __forceinline__ uint32_t smem_u32(const void* p) {
    return (uint32_t)__cvta_generic_to_shared(p);
}
__device__ __forceinline__ void cp_async16(uint32_t dst, const void* src) {
    asm volatile("cp.async.cg.shared.global [%0], [%1], 16;"
                 :: "r"(dst), "l"(src) : "memory");
}
#define CP_COMMIT() asm volatile("cp.async.commit_group;" ::: "memory")
#define CP_WAIT0()  asm volatile("cp.async.wait_group 0;" ::: "memory")

__device__ __forceinline__ void ldsm_x4(uint32_t& r0, uint32_t& r1,
                                        uint32_t& r2, uint32_t& r3, uint32_t a) {
    asm volatile("ldmatrix.sync.aligned.m8n8.x4.shared.b16 {%0,%1,%2,%3}, [%4];"
                 : "=r"(r0), "=r"(r1), "=r"(r2), "=r"(r3) : "r"(a));
}
__device__ __forceinline__ void ldsm_x4t(uint32_t& r0, uint32_t& r1,
                                         uint32_t& r2, uint32_t& r3, uint32_t a) {
    asm volatile("ldmatrix.sync.aligned.m8n8.x4.trans.shared.b16 {%0,%1,%2,%3}, [%4];"
                 : "=r"(r0), "=r"(r1), "=r"(r2), "=r"(r3) : "r"(a));
}
__device__ __forceinline__ void mma_fp16(float* d, const uint32_t* a,
                                         uint32_t b0, uint32_t b1) {
    asm volatile("mma.sync.aligned.m16n8k16.row.col.f32.f16.f16.f32 "
                 "{%0,%1,%2,%3}, {%4,%5,%6,%7}, {%8,%9}, {%0,%1,%2,%3};"
                 : "+f"(d[0]), "+f"(d[1]), "+f"(d[2]), "+f"(d[3])
                 : "r"(a[0]), "r"(a[1]), "r"(a[2]), "r"(a[3]),
                   "r"(b0), "r"(b1));
}
__device__ __forceinline__ float2 h2f2(uint32_t h) {
    __half2 v = *reinterpret_cast<__half2*>(&h);
    return __half22float2(v);
}

// ---------------------------------------------------------------------------
// prep: W1/W2 -> fp16 B-fragment images (R12-proven mapping).
// ---------------------------------------------------------------------------
__global__ void prep_kernel(const float* __restrict__ W1, const float* __restrict__ W2)
{
    int i = blockIdx.x * blockDim.x + threadIdx.x;
    if (i >= 12288) return;
    int lane = i & 31, p = (i >> 5) & 3, s = (i >> 7) & 3, wn = (i >> 9) & 3, kc = i >> 11;
    int g = lane >> 2, tq = lane & 3;
    int n0 = wn*64 + p*16 + g;
    int kk = s*16 + 2*tq;
    const float* W = (kc < 2) ? W1 : W2;
    int k0 = (kc < 2) ? kc*64 : (kc - 2)*64;

    __half2 w0 = __floats2half2_rn(W[(size_t)(k0+kk  )*256 + n0],   W[(size_t)(k0+kk+1)*256 + n0]);
    __half2 w1 = __floats2half2_rn(W[(size_t)(k0+kk+8)*256 + n0],   W[(size_t)(k0+kk+9)*256 + n0]);
    __half2 w2 = __floats2half2_rn(W[(size_t)(k0+kk  )*256 + n0+8], W[(size_t)(k0+kk+1)*256 + n0+8]);
    __half2 w3 = __floats2half2_rn(W[(size_t)(k0+kk+8)*256 + n0+8], W[(size_t)(k0+kk+9)*256 + n0+8]);
    uint4 o;
    o.x = *reinterpret_cast<uint32_t*>(&w0);
    o.y = *reinterpret_cast<uint32_t*>(&w1);
    o.z = *reinterpret_cast<uint32_t*>(&w2);
    o.w = *reinterpret_cast<uint32_t*>(&w3);
    g_Wf[i] = o;
}

// ---------------------------------------------------------------------------
// phi kernel: R14 structure; silu via __fdividef (MUFU rcp, no div.rn).
// ---------------------------------------------------------------------------
#define PHI_SMEM 37120

__global__ void __launch_bounds__(256, 2) phi_mma_kernel(
    const float* __restrict__ q, const float* __restrict__ k,
    const float* __restrict__ b1, const float* __restrict__ b2)
{
    extern __shared__ char smc[];
    __half* sAh = reinterpret_cast<__half*>(smc);
    float* sB1  = reinterpret_cast<float*>(smc + 33792);
    float* sB2  = reinterpret_cast<float*>(smc + 34816);
    float* sPrt = reinterpret_cast<float*>(smc + 35840);
    float* sInv = reinterpret_cast<float*>(smc + 36864);
    const uint32_t abase = smem_u32(smc);

    const int tid  = threadIdx.x;
    const int wid  = tid >> 5;
    const int lane = tid & 31;
    const int g    = lane >> 2;
    const int tq   = lane & 3;
    const int wm   = wid & 1;
    const int wn   = wid >> 1;

    const int bid = blockIdx.x;
    const bool isq = (bid < 2048);
    const float* src = isq ? q : k;
    const int tok0 = (bid & 2047) * 64;

    {
        const float4* s4 = reinterpret_cast<const float4*>(src + (size_t)tok0 * DD);
        #pragma unroll
        for (int l = 0; l < 8; ++l) {
            int id  = tid + l * 256;
            int row = id >> 5, c4 = id & 31;
            float4 v = s4[row * 32 + c4];
            __half2* p = reinterpret_cast<__half2*>(sAh + row*136 + c4*4);
            p[0] = __floats2half2_rn(v.x, v.y);
            p[1] = __floats2half2_rn(v.z, v.w);
        }
    }
    sB1[tid] = b1[tid];
    sB2[tid] = b2[tid];
    __syncthreads();

    float acc[2][8][4];
    #pragma unroll
    for (int mt = 0; mt < 2; ++mt)
        #pragma unroll
        for (int nt = 0; nt < 8; ++nt)
            #pragma unroll
            for (int e = 0; e < 4; ++e) acc[mt][nt][e] = 0.f;

    const int amrow   = wm*32 + (lane & 15);
    const int acoladd = ((lane >> 4) << 3);
    const int wfbase = wn*512 + lane;

    uint4 bv[2][4];
    #pragma unroll
    for (int p = 0; p < 4; ++p) bv[0][p] = g_Wf[wfbase + p*32];

    #pragma unroll
    for (int kc = 0; kc < 6; ++kc) {
        if (kc == 2) {
            __syncthreads();
            #pragma unroll
            for (int mt = 0; mt < 2; ++mt)
                #pragma unroll
                for (int nt = 0; nt < 8; ++nt) {
                    const int col = wn*64 + nt*8 + tq*2;
                    #pragma unroll
                    for (int h = 0; h < 2; ++h) {
                        const int row = wm*32 + mt*16 + 8*h + g;
                        float x0 = acc[mt][nt][h*2]   + sB1[col];
                        float x1 = acc[mt][nt][h*2+1] + sB1[col+1];
                        float s0 = __fdividef(x0, 1.f + __expf(-x0));
                        float s1 = __fdividef(x1, 1.f + __expf(-x1));
                        *reinterpret_cast<__half2*>(sAh + row*264 + col) =
                            __floats2half2_rn(s0, s1);
                        acc[mt][nt][h*2] = 0.f;
                        acc[mt][nt][h*2+1] = 0.f;
                    }
                }
            __syncthreads();
        }

        #pragma unroll
        for (int s = 0; s < 4; ++s) {
            const int step = kc*4 + s;
            const int cur  = step & 1;

            if (step < 23) {
                const int ns = step + 1;
                const int nbase = (ns >> 2) * 2048 + ((ns & 3) * 128) + wfbase;
                #pragma unroll
                for (int p = 0; p < 4; ++p)
                    bv[cur ^ 1][p] = g_Wf[nbase + p*32];
            }

            const bool s1s = (kc < 2);
            const int astr = s1s ? 136 : 264;
            const int kbase = (s1s ? kc*64 : (kc - 2)*64) + s*16;
            uint32_t a[2][4];
            #pragma unroll
            for (int mt = 0; mt < 2; ++mt) {
                uint32_t ad = abase +
                    (uint32_t)(((amrow + mt*16) * astr) + kbase + acoladd) * 2u;
                ldsm_x4(a[mt][0], a[mt][1], a[mt][2], a[mt][3], ad);
            }

            #pragma unroll
            for (int p = 0; p < 4; ++p) {
                const uint4 b = bv[cur][p];
                mma_fp16(acc[0][2*p],   a[0], b.x, b.y);
                mma_fp16(acc[0][2*p+1], a[0], b.z, b.w);
                mma_fp16(acc[1][2*p],   a[1], b.x, b.y);
                mma_fp16(acc[1][2*p+1], a[1], b.z, b.w);
            }
        }
    }

    // ===== epilogue 2: p = elu(acc + b2)+1, row L2 norm =====
    float ss[2][2] = {};
    #pragma unroll
    for (int mt = 0; mt < 2; ++mt)
        #pragma unroll
        for (int nt = 0; nt < 8; ++nt) {
            const int col = wn*64 + nt*8 + tq*2;
            #pragma unroll
            for (int h = 0; h < 2; ++h)
                #pragma unroll
                for (int pr = 0; pr < 2; ++pr) {
                    float x = acc[mt][nt][h*2+pr] + sB2[col+pr];
                    float p = (x > 0.f) ? (x + 1.f) : __expf(x);
                    acc[mt][nt][h*2+pr] = p;
                    ss[mt][h] = fmaf(p, p, ss[mt][h]);
                }
        }
    #pragma unroll
    for (int m = 1; m <= 2; m <<= 1)
        #pragma unroll
        for (int mt = 0; mt < 2; ++mt)
            #pragma unroll
            for (int h = 0; h < 2; ++h)
                ss[mt][h] += __shfl_xor_sync(0xffffffffu, ss[mt][h], m);
    if (tq == 0) {
        #pragma unroll
        for (int mt = 0; mt < 2; ++mt)
            #pragma unroll
            for (int h = 0; h < 2; ++h)
                sPrt[wn*64 + wm*32 + mt*16 + 8*h + g] = ss[mt][h];
    }
    __syncthreads();
    if (tid < 64)
        sInv[tid] = __fdividef(1.f, sqrtf(sPrt[tid] + sPrt[64+tid] +
                                          sPrt[128+tid] + sPrt[192+tid]) + 1e-6f);
    __syncthreads();

    if (isq) {
        const int tb0 = (tok0 >> 4) + wm*2;
        #pragma unroll
        for (int mt = 0; mt < 2; ++mt) {
            const float inv0 = sInv[wm*32 + mt*16 + g];
            const float inv1 = sInv[wm*32 + mt*16 + 8 + g];
            const int tb = tb0 + mt;
            #pragma unroll
            for (int np = 0; np < 4; ++np) {
                const int ntE = 2*np, ntO = 2*np + 1;
                __half2 hx = __floats2half2_rn(acc[mt][ntE][0]*inv0, acc[mt][ntE][1]*inv0);
                __half2 hy = __floats2half2_rn(acc[mt][ntE][2]*inv1, acc[mt][ntE][3]*inv1);
                __half2 hz = __floats2half2_rn(acc[mt][ntO][0]*inv0, acc[mt][ntO][1]*inv0);
                __half2 hw = __floats2half2_rn(acc[mt][ntO][2]*inv1, acc[mt][ntO][3]*inv1);
                uint4 o;
                o.x = *reinterpret_cast<uint32_t*>(&hx);
                o.y = *reinterpret_cast<uint32_t*>(&hy);
                o.z = *reinterpret_cast<uint32_t*>(&hz);
                o.w = *reinterpret_cast<uint32_t*>(&hw);
                g_phiqf[((size_t)tb*16 + (wn*4 + np))*32 + lane] = o;
            }
        }
    } else {
        #pragma unroll
        for (int mt = 0; mt < 2; ++mt)
            #pragma unroll
            for (int h = 0; h < 2; ++h) {
                const int row = wm*32 + mt*16 + 8*h + g;
                const float inv = sInv[row];
                __half* dr = g_phi_k + (size_t)(tok0 + row) * FF;
                #pragma unroll
                for (int nt = 0; nt < 8; ++nt) {
                    const int col = wn*64 + nt*8 + tq*2;
                    *reinterpret_cast<__half2*>(dr + col) =
                        __floats2half2_rn(acc[mt][nt][h*2] * inv,
                                          acc[mt][nt][h*2+1] * inv);
                }
            }
    }
}

// ---------------------------------------------------------------------------
// kv kernel: R13/14 structure; ksum now via mma against ones-B fragment
// (reuses already-loaded A fragments; wn==0 warps only, exact row sums).
// ---------------------------------------------------------------------------
#define KV_SMEM 34816
#define ONES_H2 0x3C003C00u

__global__ void __launch_bounds__(512, 2) kv_mma_kernel(const float* __restrict__ v)
{
    extern __shared__ char kvc[];
    const uint32_t sbase = smem_u32(kvc);

    const int hh = blockIdx.x;
    const int f0 = blockIdx.y * 128;
    const int ks = blockIdx.z;
    const int tid  = threadIdx.x;
    const int lane = tid & 31;
    const int wid  = tid >> 5;
    const int g  = lane >> 2;
    const int tq = lane & 3;
    const int wm = wid & 3;
    const int wn = wid >> 2;

    const __half* pbase = g_phi_k + ((size_t)hh * NSEQ + (size_t)ks * 1024) * FF + f0;
    const float*  vbase = v       + ((size_t)hh * NSEQ + (size_t)ks * 1024) * DD;

    const int vrow = tid >> 4;
    const int vseg = tid & 15;
    const uint32_t vsts_off = (uint32_t)(vrow*272 + vseg*16);

    auto issueP = [&](int b, int slot) {
        uint32_t base = sbase + (uint32_t)slot * 17408u;
        cp_async16(base + vrow*272 + vseg*16,
                   pbase + (size_t)(b*32 + vrow)*FF + vseg*8);
        CP_COMMIT();
    };
    auto ldgV = [&](int b, float4& v0, float4& v1) {
        const float4* p = reinterpret_cast<const float4*>(
            vbase + (size_t)(b*32 + vrow)*DD + vseg*8);
        v0 = p[0]; v1 = p[1];
    };

    float4 va0, va1;
    ldgV(0, va0, va1);
    issueP(0, 0);

    float acc[2][4][4];
    #pragma unroll
    for (int mt = 0; mt < 2; ++mt)
        #pragma unroll
        for (int nt = 0; nt < 4; ++nt)
            #pragma unroll
            for (int e = 0; e < 4; ++e) acc[mt][nt][e] = 0.f;
    float ksa[2][4] = {};   // ones-B mma accumulators (wn==0 warps)

    const int aseq = ((lane >> 4) << 3) + (lane & 7);
    const int afc  = wm*32 + ((lane >> 3) & 1) * 8;
    const int bseq = ((lane >> 3) & 1) * 8 + (lane & 7);
    const int bdc  = wn*32 + ((lane >> 4) << 3);

    for (int b = 0; b < 32; ++b) {
        {
            __half2 h0 = __floats2half2_rn(va0.x, va0.y);
            __half2 h1 = __floats2half2_rn(va0.z, va0.w);
            __half2 h2 = __floats2half2_rn(va1.x, va1.y);
            __half2 h3 = __floats2half2_rn(va1.z, va1.w);
            uint32_t addr = sbase + (uint32_t)(b & 1)*17408u + 8704u + vsts_off;
            asm volatile("st.shared.v4.b32 [%0], {%1,%2,%3,%4};" :: "r"(addr),
                "r"(*reinterpret_cast<uint32_t*>(&h0)),
                "r"(*reinterpret_cast<uint32_t*>(&h1)),
                "r"(*reinterpret_cast<uint32_t*>(&h2)),
                "r"(*reinterpret_cast<uint32_t*>(&h3)) : "memory");
        }
        CP_WAIT0();
        __syncthreads();
        if (b < 31) { issueP(b + 1, (b + 1) & 1); ldgV(b + 1, va0, va1); }

        const uint32_t pb = sbase + (uint32_t)(b & 1) * 17408u;
        const uint32_t vb = pb + 8704u;

        uint32_t a[2][2][4];
        #pragma unroll
        for (int s = 0; s < 2; ++s)
            #pragma unroll
            for (int mt = 0; mt < 2; ++mt) {
                uint32_t ad = pb + (uint32_t)(((s*16 + aseq) * 136) + afc + mt*16) * 2u;
                ldsm_x4t(a[mt][s][0], a[mt][s][1], a[mt][s][2], a[mt][s][3], ad);
            }
        if (wn == 0) {
            #pragma unroll
            for (int s = 0; s < 2; ++s)
                #pragma unroll
                for (int mt = 0; mt < 2; ++mt)
                    mma_fp16(ksa[mt], a[mt][s], ONES_H2, ONES_H2);
        }
        #pragma unroll
        for (int s = 0; s < 2; ++s)
            #pragma unroll
            for (int p = 0; p < 2; ++p) {
                uint32_t b0, b1v, b2, b3;
                uint32_t bd = vb + (uint32_t)(((s*16 + bseq) * 136) + bdc + p*16) * 2u;
                ldsm_x4t(b0, b1v, b2, b3, bd);
                mma_fp16(acc[0][2*p],   a[0][s], b0, b1v);
                mma_fp16(acc[0][2*p+1], a[0][s], b2, b3);
                mma_fp16(acc[1][2*p],   a[1][s], b0, b1v);
                mma_fp16(acc[1][2*p+1], a[1][s], b2, b3);
            }
    }

    float* outp = g_kvp + ((size_t)ks * BH + hh) * FF * DD;
    #pragma unroll
    for (int mt = 0; mt < 2; ++mt)
        #pragma unroll
        for (int h = 0; h < 2; ++h) {
            const int f = f0 + wm*32 + mt*16 + 8*h + g;
            #pragma unroll
            for (int nt = 0; nt < 4; ++nt) {
                const int d = wn*32 + nt*8 + tq*2;
                *reinterpret_cast<float2*>(outp + (size_t)f * DD + d) =
                    make_float2(acc[mt][nt][h*2], acc[mt][nt][h*2+1]);
            }
        }
    // ksum partials: mma rows m = wm*32 + mt*16 + {g, g+8}; cols identical.
    if (wn == 0 && tq == 0) {
        float* kout = g_ksp + ((size_t)ks * BH + hh) * FF + f0;
        #pragma unroll
        for (int mt = 0; mt < 2; ++mt) {
            kout[wm*32 + mt*16 + g]     = ksa[mt][0];
            kout[wm*32 + mt*16 + 8 + g] = ksa[mt][2];
        }
    }
}

// ---------------------------------------------------------------------------
// reduce kernel (unchanged)
// ---------------------------------------------------------------------------
__global__ void reduce_kernel()
{
    const int NKV4 = BH * FF * DD / 4;
    const int NKS  = BH * FF;
    int i = blockIdx.x * blockDim.x + threadIdx.x;
    if (i < NKV4) {
        float4 s = make_float4(0.f, 0.f, 0.f, 0.f);
        #pragma unroll
        for (int p = 0; p < KSPLIT; ++p) {
            float4 t = reinterpret_cast<const float4*>(g_kvp)[(size_t)p * NKV4 + i];
            s.x += t.x; s.y += t.y; s.z += t.z; s.w += t.w;
        }
        __half2* o = reinterpret_cast<__half2*>(g_kvh + (size_t)i*4);
        o[0] = __floats2half2_rn(s.x, s.y);
        o[1] = __floats2half2_rn(s.z, s.w);
    } else {
        int j = i - NKV4;
        if (j < NKS) {
            float s = 0.f;
            #pragma unroll
            for (int p = 0; p < KSPLIT; ++p) s += g_ksp[(size_t)p * NKS + j];
            g_ksum[j] = s;
        }
    }
}

// ---------------------------------------------------------------------------
// qkv kernel (unchanged from R14 except fast reciprocal in epilogue).
// ---------------------------------------------------------------------------
#define QSLOT 8704u
#define QKV_SMEM 17408

__global__ void __launch_bounds__(512) qkv_mma_kernel(float* __restrict__ out)
{
    extern __shared__ char qc[];
    __shared__ float sKs[2][32];
    __shared__ float sDen[256];
    const uint32_t sbase = smem_u32(qc);

    const int hh = blockIdx.x;
    const int m0 = blockIdx.y * 256;
    const int tid  = threadIdx.x;
    const int lane = tid & 31;
    const int wid  = tid >> 5;
    const int g  = lane >> 2;
    const int tq = lane & 3;
    const int wm = wid & 7;
    const int wn = wid >> 3;

    const __half* bgb = g_kvh + (size_t)hh * FF * DD;
    const size_t fbase = ((size_t)hh*256 + (m0 >> 4) + wm*2) * 16 * 32 + lane;

    auto issueB = [&](int kc, int slot) {
        uint32_t base = sbase + (uint32_t)slot * QSLOT;
        int row = tid >> 4, seg = tid & 15;
        cp_async16(base + row*272 + seg*16,
                   bgb + (size_t)(kc*32 + row)*DD + seg*8);
        CP_COMMIT();
    };

    issueB(0, 0);
    if (tid < 32) sKs[0][tid] = g_ksum[(size_t)hh * FF + tid];

    uint4 fa[2][4];
    #pragma unroll
    for (int mt = 0; mt < 2; ++mt)
        #pragma unroll
        for (int s = 0; s < 2; ++s)
            fa[0][mt*2+s] = g_phiqf[fbase + ((size_t)mt*16 + s)*32];

    float acc[2][8][4];
    #pragma unroll
    for (int mt = 0; mt < 2; ++mt)
        #pragma unroll
        for (int nt = 0; nt < 8; ++nt)
            #pragma unroll
            for (int e = 0; e < 4; ++e) acc[mt][nt][e] = 0.f;
    float den4[2][2] = {};

    const int bseq = ((lane >> 3) & 1) * 8 + (lane & 7);
    const int bdc  = wn*64 + ((lane >> 4) << 3);

    for (int kc = 0; kc < 8; ++kc) {
        const int cur = kc & 1;
        if (kc < 7) {
            #pragma unroll
            for (int mt = 0; mt < 2; ++mt)
                #pragma unroll
                for (int s = 0; s < 2; ++s)
                    fa[cur ^ 1][mt*2+s] =
                        g_phiqf[fbase + ((size_t)mt*16 + (kc+1)*2 + s)*32];
        }

        CP_WAIT0();
        __syncthreads();
        if (kc < 7) {
            issueB(kc + 1, (kc + 1) & 1);
            if (tid < 32)
                sKs[(kc+1) & 1][tid] = g_ksum[(size_t)hh * FF + (kc+1)*32 + tid];
        }

        const uint32_t bb = sbase + (uint32_t)cur * QSLOT;
        const float* ks = sKs[cur];

        if (wn == 0) {
            #pragma unroll
            for (int mt = 0; mt < 2; ++mt)
                #pragma unroll
                for (int s = 0; s < 2; ++s) {
                    const uint4 f = fa[cur][mt*2+s];
                    const int k0 = s*16 + 2*tq;
                    float2 xv = h2f2(f.x), yv = h2f2(f.y);
                    float2 zv = h2f2(f.z), wv = h2f2(f.w);
                    den4[mt][0] = fmaf(xv.x, ks[k0],   den4[mt][0]);
                    den4[mt][0] = fmaf(xv.y, ks[k0+1], den4[mt][0]);
                    den4[mt][0] = fmaf(zv.x, ks[k0+8], den4[mt][0]);
                    den4[mt][0] = fmaf(zv.y, ks[k0+9], den4[mt][0]);
                    den4[mt][1] = fmaf(yv.x, ks[k0],   den4[mt][1]);
                    den4[mt][1] = fmaf(yv.y, ks[k0+1], den4[mt][1]);
                    den4[mt][1] = fmaf(wv.x, ks[k0+8], den4[mt][1]);
                    den4[mt][1] = fmaf(wv.y, ks[k0+9], den4[mt][1]);
                }
        }

        #pragma unroll
        for (int s = 0; s < 2; ++s) {
            const uint32_t* a0 = reinterpret_cast<const uint32_t*>(&fa[cur][s]);
            const uint32_t* a1 = reinterpret_cast<const uint32_t*>(&fa[cur][2+s]);
            #pragma unroll
            for (int p = 0; p < 4; ++p) {
                uint32_t b0, b1v, b2, b3;
                uint32_t bd = bb + (uint32_t)(((s*16 + bseq) * 136) + bdc + p*16) * 2u;
                ldsm_x4t(b0, b1v, b2, b3, bd);
                mma_fp16(acc[0][2*p],   a0, b0, b1v);
                mma_fp16(acc[0][2*p+1], a0, b2, b3);
                mma_fp16(acc[1][2*p],   a1, b0, b1v);
                mma_fp16(acc[1][2*p+1], a1, b2, b3);
            }
        }
    }

    #pragma unroll
    for (int m = 1; m <= 2; m <<= 1)
        #pragma unroll
        for (int mt = 0; mt < 2; ++mt)
            #pragma unroll
            for (int h = 0; h < 2; ++h)
                den4[mt][h] += __shfl_xor_sync(0xffffffffu, den4[mt][h], m);
    if (wn == 0 && tq == 0) {
        #pragma unroll
        for (int mt = 0; mt < 2; ++mt) {
            sDen[wm*32 + mt*16 + g]     = den4[mt][0];
            sDen[wm*32 + mt*16 + 8 + g] = den4[mt][1];
        }
    }
    __syncthreads();

    float* op = out + ((size_t)hh * NSEQ + m0) * DD;
    #pragma unroll
    for (int mt = 0; mt < 2; ++mt)
        #pragma unroll
        for (int h = 0; h < 2; ++h) {
            const int row = wm*32 + mt*16 + 8*h + g;
            const float invd = __fdividef(1.f, fmaxf(sDen[row], 1e-6f));
            #pragma unroll
            for (int nt = 0; nt < 8; ++nt) {
                const int d = wn*64 + nt*8 + tq*2;
                *reinterpret_cast<float2*>(op + (size_t)row * DD + d) =
                    make_float2(acc[mt][nt][h*2] * invd, acc[mt][nt][h*2+1] * invd);
            }
        }
}

// ---------------------------------------------------------------------------
extern "C" void kernel_launch(void* const* d_in, const int* in_sizes, int n_in,
                              void* d_out, int out_size)
{
    (void)in_sizes; (void)n_in; (void)out_size;
    const float* q  = (const float*)d_in[0];
    const float* k  = (const float*)d_in[1];
    const float* v  = (const float*)d_in[2];
    const float* W1 = (const float*)d_in[3];
    const float* b1 = (const float*)d_in[4];
    const float* W2 = (const float*)d_in[5];
    const float* b2 = (const float*)d_in[6];
    float* out = (float*)d_out;

    cudaFuncSetAttribute(phi_mma_kernel, cudaFuncAttributeMaxDynamicSharedMemorySize, PHI_SMEM);
    cudaFuncSetAttribute(kv_mma_kernel,  cudaFuncAttributeMaxDynamicSharedMemorySize, KV_SMEM);
    cudaFuncSetAttribute(qkv_mma_kernel, cudaFuncAttributeMaxDynamicSharedMemorySize, QKV_SMEM);

    prep_kernel<<<48, 256>>>(W1, W2);
    phi_mma_kernel<<<4096, 256, PHI_SMEM>>>(q, k, b1, b2);
    kv_mma_kernel<<<dim3(32, 2, KSPLIT), 512, KV_SMEM>>>(v);
    {
        const int total = BH*FF*DD/4 + BH*FF;
        reduce_kernel<<<(total + 255) / 256, 256>>>();
    }
    qkv_mma_kernel<<<dim3(32, 16), 512, QKV_SMEM>>>(out);
}

// round 16
// speedup vs baseline: 1.0476x; 1.0476x over previous
#include <cuda_runtime.h>
#include <cuda_fp16.h>
#include <math.h>
#include <stdint.h>

// Problem constants
#define BH    32
#define NSEQ  4096
#define DD    128
#define FF    256
#define NTOK  (BH*NSEQ)
#define KSPLIT 4

// Scratch (device globals: allocation-free rule)
__device__ uint4  g_phiqf[(size_t)(NTOK/16)*16*32];  // phi_q in A-fragment order (67MB)
__device__ __half g_phi_k[(size_t)NTOK*FF];
__device__ float  g_kvp[(size_t)KSPLIT*BH*FF*DD];
__device__ float  g_ksp[(size_t)KSPLIT*BH*FF];
__device__ __half g_kvh[(size_t)BH*FF*DD];
__device__ float  g_ksum[(size_t)BH*FF];
__device__ uint4  g_Wf[12288];            // W in mma B-fragment order (192KB, L2-resident)

// ---------------------------------------------------------------------------
// helpers
// ---------------------------------------------------------------------------
__device__ __forceinline__ uint32_t smem_u32(const void* p) {
    return (uint32_t)__cvta_generic_to_shared(p);
}
__device__ __forceinline__ void cp_async16(uint32_t dst, const void* src) {
    asm volatile("cp.async.cg.shared.global [%0], [%1], 16;"
                 :: "r"(dst), "l"(src) : "memory");
}
#define CP_COMMIT() asm volatile("cp.async.commit_group;" ::: "memory")
#define CP_WAIT0()  asm volatile("cp.async.wait_group 0;" ::: "memory")

__device__ __forceinline__ void ldsm_x4(uint32_t& r0, uint32_t& r1,
                                        uint32_t& r2, uint32_t& r3, uint32_t a) {
    asm volatile("ldmatrix.sync.aligned.m8n8.x4.shared.b16 {%0,%1,%2,%3}, [%4];"
                 : "=r"(r0), "=r"(r1), "=r"(r2), "=r"(r3) : "r"(a));
}
__device__ __forceinline__ void ldsm_x4t(uint32_t& r0, uint32_t& r1,
                                         uint32_t& r2, uint32_t& r3, uint32_t a) {
    asm volatile("ldmatrix.sync.aligned.m8n8.x4.trans.shared.b16 {%0,%1,%2,%3}, [%4];"
                 : "=r"(r0), "=r"(r1), "=r"(r2), "=r"(r3) : "r"(a));
}
__device__ __forceinline__ void mma_fp16(float* d, const uint32_t* a,
                                         uint32_t b0, uint32_t b1) {
    asm volatile("mma.sync.aligned.m16n8k16.row.col.f32.f16.f16.f32 "
                 "{%0,%1,%2,%3}, {%4,%5,%6,%7}, {%8,%9}, {%0,%1,%2,%3};"
                 : "+f"(d[0]), "+f"(d[1]), "+f"(d[2]), "+f"(d[3])
                 : "r"(a[0]), "r"(a[1]), "r"(a[2]), "r"(a[3]),
                   "r"(b0), "r"(b1));
}
__device__ __forceinline__ float2 h2f2(uint32_t h) {
    __half2 v = *reinterpret_cast<__half2*>(&h);
    return __half22float2(v);
}

// ---------------------------------------------------------------------------
// prep: W1/W2 -> fp16 B-fragment images (R12-proven mapping).
// ---------------------------------------------------------------------------
__global__ void prep_kernel(const float* __restrict__ W1, const float* __restrict__ W2)
{
    int i = blockIdx.x * blockDim.x + threadIdx.x;
    if (i >= 12288) return;
    int lane = i & 31, p = (i >> 5) & 3, s = (i >> 7) & 3, wn = (i >> 9) & 3, kc = i >> 11;
    int g = lane >> 2, tq = lane & 3;
    int n0 = wn*64 + p*16 + g;
    int kk = s*16 + 2*tq;
    const float* W = (kc < 2) ? W1 : W2;
    int k0 = (kc < 2) ? kc*64 : (kc - 2)*64;

    __half2 w0 = __floats2half2_rn(W[(size_t)(k0+kk  )*256 + n0],   W[(size_t)(k0+kk+1)*256 + n0]);
    __half2 w1 = __floats2half2_rn(W[(size_t)(k0+kk+8)*256 + n0],   W[(size_t)(k0+kk+9)*256 + n0]);
    __half2 w2 = __floats2half2_rn(W[(size_t)(k0+kk  )*256 + n0+8], W[(size_t)(k0+kk+1)*256 + n0+8]);
    __half2 w3 = __floats2half2_rn(W[(size_t)(k0+kk+8)*256 + n0+8], W[(size_t)(k0+kk+9)*256 + n0+8]);
    uint4 o;
    o.x = *reinterpret_cast<uint32_t*>(&w0);
    o.y = *reinterpret_cast<uint32_t*>(&w1);
    o.z = *reinterpret_cast<uint32_t*>(&w2);
    o.w = *reinterpret_cast<uint32_t*>(&w3);
    g_Wf[i] = o;
}

// ---------------------------------------------------------------------------
// phi kernel: fp16 mma, B from fragment-ordered gmem (reg double buffer),
// phi_q written in A-fragment uint4 order, phi_k row-major.
// 64 tokens/CTA, 256 threads (8 warps, 2M x 4N), 2 CTAs/SM.
// ---------------------------------------------------------------------------
#define PHI_SMEM 37120

__global__ void __launch_bounds__(256, 2) phi_mma_kernel(
    const float* __restrict__ q, const float* __restrict__ k,
    const float* __restrict__ b1, const float* __restrict__ b2)
{
    extern __shared__ char smc[];
    __half* sAh = reinterpret_cast<__half*>(smc);
    float* sB1  = reinterpret_cast<float*>(smc + 33792);
    float* sB2  = reinterpret_cast<float*>(smc + 34816);
    float* sPrt = reinterpret_cast<float*>(smc + 35840);
    float* sInv = reinterpret_cast<float*>(smc + 36864);
    const uint32_t abase = smem_u32(smc);

    const int tid  = threadIdx.x;
    const int wid  = tid >> 5;
    const int lane = tid & 31;
    const int g    = lane >> 2;
    const int tq   = lane & 3;
    const int wm   = wid & 1;
    const int wn   = wid >> 1;

    const int bid = blockIdx.x;
    const bool isq = (bid < 2048);
    const float* src = isq ? q : k;
    const int tok0 = (bid & 2047) * 64;

    {
        const float4* s4 = reinterpret_cast<const float4*>(src + (size_t)tok0 * DD);
        #pragma unroll
        for (int l = 0; l < 8; ++l) {
            int id  = tid + l * 256;
            int row = id >> 5, c4 = id & 31;
            float4 v = s4[row * 32 + c4];
            __half2* p = reinterpret_cast<__half2*>(sAh + row*136 + c4*4);
            p[0] = __floats2half2_rn(v.x, v.y);
            p[1] = __floats2half2_rn(v.z, v.w);
        }
    }
    sB1[tid] = b1[tid];
    sB2[tid] = b2[tid];
    __syncthreads();

    float acc[2][8][4];
    #pragma unroll
    for (int mt = 0; mt < 2; ++mt)
        #pragma unroll
        for (int nt = 0; nt < 8; ++nt)
            #pragma unroll
            for (int e = 0; e < 4; ++e) acc[mt][nt][e] = 0.f;

    const int amrow   = wm*32 + (lane & 15);
    const int acoladd = ((lane >> 4) << 3);
    const int wfbase = wn*512 + lane;

    uint4 bv[2][4];
    #pragma unroll
    for (int p = 0; p < 4; ++p) bv[0][p] = g_Wf[wfbase + p*32];

    #pragma unroll
    for (int kc = 0; kc < 6; ++kc) {
        if (kc == 2) {
            __syncthreads();
            #pragma unroll
            for (int mt = 0; mt < 2; ++mt)
                #pragma unroll
                for (int nt = 0; nt < 8; ++nt) {
                    const int col = wn*64 + nt*8 + tq*2;
                    #pragma unroll
                    for (int h = 0; h < 2; ++h) {
                        const int row = wm*32 + mt*16 + 8*h + g;
                        float x0 = acc[mt][nt][h*2]   + sB1[col];
                        float x1 = acc[mt][nt][h*2+1] + sB1[col+1];
                        float s0 = x0 / (1.f + __expf(-x0));
                        float s1 = x1 / (1.f + __expf(-x1));
                        *reinterpret_cast<__half2*>(sAh + row*264 + col) =
                            __floats2half2_rn(s0, s1);
                        acc[mt][nt][h*2] = 0.f;
                        acc[mt][nt][h*2+1] = 0.f;
                    }
                }
            __syncthreads();
        }

        #pragma unroll
        for (int s = 0; s < 4; ++s) {
            const int step = kc*4 + s;
            const int cur  = step & 1;

            if (step < 23) {
                const int ns = step + 1;
                const int nbase = (ns >> 2) * 2048 + ((ns & 3) * 128) + wfbase;
                #pragma unroll
                for (int p = 0; p < 4; ++p)
                    bv[cur ^ 1][p] = g_Wf[nbase + p*32];
            }

            const bool s1s = (kc < 2);
            const int astr = s1s ? 136 : 264;
            const int kbase = (s1s ? kc*64 : (kc - 2)*64) + s*16;
            uint32_t a[2][4];
            #pragma unroll
            for (int mt = 0; mt < 2; ++mt) {
                uint32_t ad = abase +
                    (uint32_t)(((amrow + mt*16) * astr) + kbase + acoladd) * 2u;
                ldsm_x4(a[mt][0], a[mt][1], a[mt][2], a[mt][3], ad);
            }

            #pragma unroll
            for (int p = 0; p < 4; ++p) {
                const uint4 b = bv[cur][p];
                mma_fp16(acc[0][2*p],   a[0], b.x, b.y);
                mma_fp16(acc[0][2*p+1], a[0], b.z, b.w);
                mma_fp16(acc[1][2*p],   a[1], b.x, b.y);
                mma_fp16(acc[1][2*p+1], a[1], b.z, b.w);
            }
        }
    }

    // ===== epilogue 2: p = elu(acc + b2)+1, row L2 norm =====
    float ss[2][2] = {};
    #pragma unroll
    for (int mt = 0; mt < 2; ++mt)
        #pragma unroll
        for (int nt = 0; nt < 8; ++nt) {
            const int col = wn*64 + nt*8 + tq*2;
            #pragma unroll
            for (int h = 0; h < 2; ++h)
                #pragma unroll
                for (int pr = 0; pr < 2; ++pr) {
                    float x = acc[mt][nt][h*2+pr] + sB2[col+pr];
                    float p = (x > 0.f) ? (x + 1.f) : __expf(x);
                    acc[mt][nt][h*2+pr] = p;
                    ss[mt][h] = fmaf(p, p, ss[mt][h]);
                }
        }
    #pragma unroll
    for (int m = 1; m <= 2; m <<= 1)
        #pragma unroll
        for (int mt = 0; mt < 2; ++mt)
            #pragma unroll
            for (int h = 0; h < 2; ++h)
                ss[mt][h] += __shfl_xor_sync(0xffffffffu, ss[mt][h], m);
    if (tq == 0) {
        #pragma unroll
        for (int mt = 0; mt < 2; ++mt)
            #pragma unroll
            for (int h = 0; h < 2; ++h)
                sPrt[wn*64 + wm*32 + mt*16 + 8*h + g] = ss[mt][h];
    }
    __syncthreads();
    if (tid < 64)
        sInv[tid] = 1.f / (sqrtf(sPrt[tid] + sPrt[64+tid] +
                                 sPrt[128+tid] + sPrt[192+tid]) + 1e-6f);
    __syncthreads();

    if (isq) {
        const int tb0 = (tok0 >> 4) + wm*2;
        #pragma unroll
        for (int mt = 0; mt < 2; ++mt) {
            const float inv0 = sInv[wm*32 + mt*16 + g];
            const float inv1 = sInv[wm*32 + mt*16 + 8 + g];
            const int tb = tb0 + mt;
            #pragma unroll
            for (int np = 0; np < 4; ++np) {
                const int ntE = 2*np, ntO = 2*np + 1;
                __half2 hx = __floats2half2_rn(acc[mt][ntE][0]*inv0, acc[mt][ntE][1]*inv0);
                __half2 hy = __floats2half2_rn(acc[mt][ntE][2]*inv1, acc[mt][ntE][3]*inv1);
                __half2 hz = __floats2half2_rn(acc[mt][ntO][0]*inv0, acc[mt][ntO][1]*inv0);
                __half2 hw = __floats2half2_rn(acc[mt][ntO][2]*inv1, acc[mt][ntO][3]*inv1);
                uint4 o;
                o.x = *reinterpret_cast<uint32_t*>(&hx);
                o.y = *reinterpret_cast<uint32_t*>(&hy);
                o.z = *reinterpret_cast<uint32_t*>(&hz);
                o.w = *reinterpret_cast<uint32_t*>(&hw);
                g_phiqf[((size_t)tb*16 + (wn*4 + np))*32 + lane] = o;
            }
        }
    } else {
        #pragma unroll
        for (int mt = 0; mt < 2; ++mt)
            #pragma unroll
            for (int h = 0; h < 2; ++h) {
                const int row = wm*32 + mt*16 + 8*h + g;
                const float inv = sInv[row];
                __half* dr = g_phi_k + (size_t)(tok0 + row) * FF;
                #pragma unroll
                for (int nt = 0; nt < 8; ++nt) {
                    const int col = wn*64 + nt*8 + tq*2;
                    *reinterpret_cast<__half2*>(dr + col) =
                        __floats2half2_rn(acc[mt][nt][h*2] * inv,
                                          acc[mt][nt][h*2+1] * inv);
                }
            }
    }
}

// ---------------------------------------------------------------------------
// kv kernel: inline v fp32->fp16 staging, cp.async P, S=2, scalar ksum.
// ---------------------------------------------------------------------------
#define KV_SMEM 34816

__global__ void __launch_bounds__(512, 2) kv_mma_kernel(const float* __restrict__ v)
{
    extern __shared__ char kvc[];
    const uint32_t sbase = smem_u32(kvc);

    const int hh = blockIdx.x;
    const int f0 = blockIdx.y * 128;
    const int ks = blockIdx.z;
    const int tid  = threadIdx.x;
    const int lane = tid & 31;
    const int wid  = tid >> 5;
    const int g  = lane >> 2;
    const int tq = lane & 3;
    const int wm = wid & 3;
    const int wn = wid >> 2;

    const __half* pbase = g_phi_k + ((size_t)hh * NSEQ + (size_t)ks * 1024) * FF + f0;
    const float*  vbase = v       + ((size_t)hh * NSEQ + (size_t)ks * 1024) * DD;

    const int vrow = tid >> 4;
    const int vseg = tid & 15;
    const uint32_t vsts_off = (uint32_t)(vrow*272 + vseg*16);

    auto issueP = [&](int b, int slot) {
        uint32_t base = sbase + (uint32_t)slot * 17408u;
        cp_async16(base + vrow*272 + vseg*16,
                   pbase + (size_t)(b*32 + vrow)*FF + vseg*8);
        CP_COMMIT();
    };
    auto ldgV = [&](int b, float4& v0, float4& v1) {
        const float4* p = reinterpret_cast<const float4*>(
            vbase + (size_t)(b*32 + vrow)*DD + vseg*8);
        v0 = p[0]; v1 = p[1];
    };

    float4 va0, va1;
    ldgV(0, va0, va1);
    issueP(0, 0);

    float acc[2][4][4];
    #pragma unroll
    for (int mt = 0; mt < 2; ++mt)
        #pragma unroll
        for (int nt = 0; nt < 4; ++nt)
            #pragma unroll
            for (int e = 0; e < 4; ++e) acc[mt][nt][e] = 0.f;
    float ksacc = 0.f;

    const int aseq = ((lane >> 4) << 3) + (lane & 7);
    const int afc  = wm*32 + ((lane >> 3) & 1) * 8;
    const int bseq = ((lane >> 3) & 1) * 8 + (lane & 7);
    const int bdc  = wn*32 + ((lane >> 4) << 3);

    for (int b = 0; b < 32; ++b) {
        {
            __half2 h0 = __floats2half2_rn(va0.x, va0.y);
            __half2 h1 = __floats2half2_rn(va0.z, va0.w);
            __half2 h2 = __floats2half2_rn(va1.x, va1.y);
            __half2 h3 = __floats2half2_rn(va1.z, va1.w);
            uint32_t addr = sbase + (uint32_t)(b & 1)*17408u + 8704u + vsts_off;
            asm volatile("st.shared.v4.b32 [%0], {%1,%2,%3,%4};" :: "r"(addr),
                "r"(*reinterpret_cast<uint32_t*>(&h0)),
                "r"(*reinterpret_cast<uint32_t*>(&h1)),
                "r"(*reinterpret_cast<uint32_t*>(&h2)),
                "r"(*reinterpret_cast<uint32_t*>(&h3)) : "memory");
        }
        CP_WAIT0();
        __syncthreads();
        if (b < 31) { issueP(b + 1, (b + 1) & 1); ldgV(b + 1, va0, va1); }

        const uint32_t pb = sbase + (uint32_t)(b & 1) * 17408u;
        const uint32_t vb = pb + 8704u;
        const __half* sP = reinterpret_cast<const __half*>(kvc + (b & 1) * 17408);

        if (tid < 128) {
            #pragma unroll
            for (int r = 0; r < 32; ++r)
                ksacc += __half2float(sP[r*136 + tid]);
        }

        uint32_t a[2][2][4];
        #pragma unroll
        for (int s = 0; s < 2; ++s)
            #pragma unroll
            for (int mt = 0; mt < 2; ++mt) {
                uint32_t ad = pb + (uint32_t)(((s*16 + aseq) * 136) + afc + mt*16) * 2u;
                ldsm_x4t(a[mt][s][0], a[mt][s][1], a[mt][s][2], a[mt][s][3], ad);
            }
        #pragma unroll
        for (int s = 0; s < 2; ++s)
            #pragma unroll
            for (int p = 0; p < 2; ++p) {
                uint32_t b0, b1v, b2, b3;
                uint32_t bd = vb + (uint32_t)(((s*16 + bseq) * 136) + bdc + p*16) * 2u;
                ldsm_x4t(b0, b1v, b2, b3, bd);
                mma_fp16(acc[0][2*p],   a[0][s], b0, b1v);
                mma_fp16(acc[0][2*p+1], a[0][s], b2, b3);
                mma_fp16(acc[1][2*p],   a[1][s], b0, b1v);
                mma_fp16(acc[1][2*p+1], a[1][s], b2, b3);
            }
    }

    float* outp = g_kvp + ((size_t)ks * BH + hh) * FF * DD;
    #pragma unroll
    for (int mt = 0; mt < 2; ++mt)
        #pragma unroll
        for (int h = 0; h < 2; ++h) {
            const int f = f0 + wm*32 + mt*16 + 8*h + g;
            #pragma unroll
            for (int nt = 0; nt < 4; ++nt) {
                const int d = wn*32 + nt*8 + tq*2;
                *reinterpret_cast<float2*>(outp + (size_t)f * DD + d) =
                    make_float2(acc[mt][nt][h*2], acc[mt][nt][h*2+1]);
            }
        }
    if (tid < 128)
        g_ksp[((size_t)ks * BH + hh) * FF + f0 + tid] = ksacc;
}

// ---------------------------------------------------------------------------
// reduce kernel
// ---------------------------------------------------------------------------
__global__ void reduce_kernel()
{
    const int NKV4 = BH * FF * DD / 4;
    const int NKS  = BH * FF;
    int i = blockIdx.x * blockDim.x + threadIdx.x;
    if (i < NKV4) {
        float4 s = make_float4(0.f, 0.f, 0.f, 0.f);
        #pragma unroll
        for (int p = 0; p < KSPLIT; ++p) {
            float4 t = reinterpret_cast<const float4*>(g_kvp)[(size_t)p * NKV4 + i];
            s.x += t.x; s.y += t.y; s.z += t.z; s.w += t.w;
        }
        __half2* o = reinterpret_cast<__half2*>(g_kvh + (size_t)i*4);
        o[0] = __floats2half2_rn(s.x, s.y);
        o[1] = __floats2half2_rn(s.z, s.w);
    } else {
        int j = i - NKV4;
        if (j < NKS) {
            float s = 0.f;
            #pragma unroll
            for (int p = 0; p < KSPLIT; ++p) s += g_ksp[(size_t)p * NKS + j];
            g_ksum[j] = s;
        }
    }
}

// ---------------------------------------------------------------------------
// qkv kernel: A fragments LDG'd from g_phiqf (reg double buffer), B via
// cp.async + ldsm.trans, den from fragments. grid (32, 16), 512 threads.
// ---------------------------------------------------------------------------
#define QSLOT 8704u
#define QKV_SMEM 17408

__global__ void __launch_bounds__(512) qkv_mma_kernel(float* __restrict__ out)
{
    extern __shared__ char qc[];
    __shared__ float sKs[2][32];
    __shared__ float sDen[256];
    const uint32_t sbase = smem_u32(qc);

    const int hh = blockIdx.x;
    const int m0 = blockIdx.y * 256;
    const int tid  = threadIdx.x;
    const int lane = tid & 31;
    const int wid  = tid >> 5;
    const int g  = lane >> 2;
    const int tq = lane & 3;
    const int wm = wid & 7;
    const int wn = wid >> 3;

    const __half* bgb = g_kvh + (size_t)hh * FF * DD;
    const size_t fbase = ((size_t)hh*256 + (m0 >> 4) + wm*2) * 16 * 32 + lane;

    auto issueB = [&](int kc, int slot) {
        uint32_t base = sbase + (uint32_t)slot * QSLOT;
        int row = tid >> 4, seg = tid & 15;
        cp_async16(base + row*272 + seg*16,
                   bgb + (size_t)(kc*32 + row)*DD + seg*8);
        CP_COMMIT();
    };

    issueB(0, 0);
    if (tid < 32) sKs[0][tid] = g_ksum[(size_t)hh * FF + tid];

    uint4 fa[2][4];
    #pragma unroll
    for (int mt = 0; mt < 2; ++mt)
        #pragma unroll
        for (int s = 0; s < 2; ++s)
            fa[0][mt*2+s] = g_phiqf[fbase + ((size_t)mt*16 + s)*32];

    float acc[2][8][4];
    #pragma unroll
    for (int mt = 0; mt < 2; ++mt)
        #pragma unroll
        for (int nt = 0; nt < 8; ++nt)
            #pragma unroll
            for (int e = 0; e < 4; ++e) acc[mt][nt][e] = 0.f;
    float den4[2][2] = {};

    const int bseq = ((lane >> 3) & 1) * 8 + (lane & 7);
    const int bdc  = wn*64 + ((lane >> 4) << 3);

    for (int kc = 0; kc < 8; ++kc) {
        const int cur = kc & 1;
        if (kc < 7) {
            #pragma unroll
            for (int mt = 0; mt < 2; ++mt)
                #pragma unroll
                for (int s = 0; s < 2; ++s)
                    fa[cur ^ 1][mt*2+s] =
                        g_phiqf[fbase + ((size_t)mt*16 + (kc+1)*2 + s)*32];
        }

        CP_WAIT0();
        __syncthreads();
        if (kc < 7) {
            issueB(kc + 1, (kc + 1) & 1);
            if (tid < 32)
                sKs[(kc+1) & 1][tid] = g_ksum[(size_t)hh * FF + (kc+1)*32 + tid];
        }

        const uint32_t bb = sbase + (uint32_t)cur * QSLOT;
        const float* ks = sKs[cur];

        if (wn == 0) {
            #pragma unroll
            for (int mt = 0; mt < 2; ++mt)
                #pragma unroll
                for (int s = 0; s < 2; ++s) {
                    const uint4 f = fa[cur][mt*2+s];
                    const int k0 = s*16 + 2*tq;
                    float2 xv = h2f2(f.x), yv = h2f2(f.y);
                    float2 zv = h2f2(f.z), wv = h2f2(f.w);
                    den4[mt][0] = fmaf(xv.x, ks[k0],   den4[mt][0]);
                    den4[mt][0] = fmaf(xv.y, ks[k0+1], den4[mt][0]);
                    den4[mt][0] = fmaf(zv.x, ks[k0+8], den4[mt][0]);
                    den4[mt][0] = fmaf(zv.y, ks[k0+9], den4[mt][0]);
                    den4[mt][1] = fmaf(yv.x, ks[k0],   den4[mt][1]);
                    den4[mt][1] = fmaf(yv.y, ks[k0+1], den4[mt][1]);
                    den4[mt][1] = fmaf(wv.x, ks[k0+8], den4[mt][1]);
                    den4[mt][1] = fmaf(wv.y, ks[k0+9], den4[mt][1]);
                }
        }

        #pragma unroll
        for (int s = 0; s < 2; ++s) {
            const uint32_t* a0 = reinterpret_cast<const uint32_t*>(&fa[cur][s]);
            const uint32_t* a1 = reinterpret_cast<const uint32_t*>(&fa[cur][2+s]);
            #pragma unroll
            for (int p = 0; p < 4; ++p) {
                uint32_t b0, b1v, b2, b3;
                uint32_t bd = bb + (uint32_t)(((s*16 + bseq) * 136) + bdc + p*16) * 2u;
                ldsm_x4t(b0, b1v, b2, b3, bd);
                mma_fp16(acc[0][2*p],   a0, b0, b1v);
                mma_fp16(acc[0][2*p+1], a0, b2, b3);
                mma_fp16(acc[1][2*p],   a1, b0, b1v);
                mma_fp16(acc[1][2*p+1], a1, b2, b3);
            }
        }
    }

    #pragma unroll
    for (int m = 1; m <= 2; m <<= 1)
        #pragma unroll
        for (int mt = 0; mt < 2; ++mt)
            #pragma unroll
            for (int h = 0; h < 2; ++h)
                den4[mt][h] += __shfl_xor_sync(0xffffffffu, den4[mt][h], m);
    if (wn == 0 && tq == 0) {
        #pragma unroll
        for (int mt = 0; mt < 2; ++mt) {
            sDen[wm*32 + mt*16 + g]     = den4[mt][0];
            sDen[wm*32 + mt*16 + 8 + g] = den4[mt][1];
        }
    }
    __syncthreads();

    float* op = out + ((size_t)hh * NSEQ + m0) * DD;
    #pragma unroll
    for (int mt = 0; mt < 2; ++mt)
        #pragma unroll
        for (int h = 0; h < 2; ++h) {
            const int row = wm*32 + mt*16 + 8*h + g;
            const float invd = 1.f / fmaxf(sDen[row], 1e-6f);
            #pragma unroll
            for (int nt = 0; nt < 8; ++nt) {
                const int d = wn*64 + nt*8 + tq*2;
                *reinterpret_cast<float2*>(op + (size_t)row * DD + d) =
                    make_float2(acc[mt][nt][h*2] * invd, acc[mt][nt][h*2+1] * invd);
            }
        }
}

// ---------------------------------------------------------------------------
extern "C" void kernel_launch(void* const* d_in, const int* in_sizes, int n_in,
                              void* d_out, int out_size)
{
    (void)in_sizes; (void)n_in; (void)out_size;
    const float* q  = (const float*)d_in[0];
    const float* k  = (const float*)d_in[1];
    const float* v  = (const float*)d_in[2];
    const float* W1 = (const float*)d_in[3];
    const float* b1 = (const float*)d_in[4];
    const float* W2 = (const float*)d_in[5];
    const float* b2 = (const float*)d_in[6];
    float* out = (float*)d_out;

    cudaFuncSetAttribute(phi_mma_kernel, cudaFuncAttributeMaxDynamicSharedMemorySize, PHI_SMEM);
    cudaFuncSetAttribute(kv_mma_kernel,  cudaFuncAttributeMaxDynamicSharedMemorySize, KV_SMEM);
    cudaFuncSetAttribute(qkv_mma_kernel, cudaFuncAttributeMaxDynamicSharedMemorySize, QKV_SMEM);

    prep_kernel<<<48, 256>>>(W1, W2);
    phi_mma_kernel<<<4096, 256, PHI_SMEM>>>(q, k, b1, b2);
    kv_mma_kernel<<<dim3(32, 2, KSPLIT), 512, KV_SMEM>>>(v);
    {
        const int total = BH*FF*DD/4 + BH*FF;
        reduce_kernel<<<(total + 255) / 256, 256>>>();
    }
    qkv_mma_kernel<<<dim3(32, 16), 512, QKV_SMEM>>>(out);
}

// round 17
// speedup vs baseline: 1.0732x; 1.0244x over previous
#include <cuda_runtime.h>
#include <cuda_fp16.h>
#include <math.h>
#include <stdint.h>

// Problem constants
#define BH    32
#define NSEQ  4096
#define DD    128
#define FF    256
#define NTOK  (BH*NSEQ)
#define KSPLIT 4

// Scratch (device globals: allocation-free rule)
__device__ uint4  g_phiqf[(size_t)(NTOK/16)*16*32];  // phi_q in A-fragment order (67MB)
__device__ __half g_phi_k[(size_t)NTOK*FF];
__device__ float  g_kvp[(size_t)KSPLIT*BH*FF*DD];
__device__ float  g_ksp[(size_t)KSPLIT*BH*FF];
__device__ __half g_kvh[(size_t)BH*FF*DD];
__device__ float  g_ksum[(size_t)BH*FF];
__device__ uint4  g_Wf[12288];            // W in mma B-fragment order (192KB, L2-resident)

// ---------------------------------------------------------------------------
// helpers
// ---------------------------------------------------------------------------
__device__ __forceinline__ uint32_t smem_u32(const void* p) {
    return (uint32_t)__cvta_generic_to_shared(p);
}
__device__ __forceinline__ void cp_async16(uint32_t dst, const void* src) {
    asm volatile("cp.async.cg.shared.global [%0], [%1], 16;"
                 :: "r"(dst), "l"(src) : "memory");
}
#define CP_COMMIT() asm volatile("cp.async.commit_group;" ::: "memory")
#define CP_WAIT0()  asm volatile("cp.async.wait_group 0;" ::: "memory")

__device__ __forceinline__ void ldsm_x4(uint32_t& r0, uint32_t& r1,
                                        uint32_t& r2, uint32_t& r3, uint32_t a) {
    asm volatile("ldmatrix.sync.aligned.m8n8.x4.shared.b16 {%0,%1,%2,%3}, [%4];"
                 : "=r"(r0), "=r"(r1), "=r"(r2), "=r"(r3) : "r"(a));
}
__device__ __forceinline__ void ldsm_x4t(uint32_t& r0, uint32_t& r1,
                                         uint32_t& r2, uint32_t& r3, uint32_t a) {
    asm volatile("ldmatrix.sync.aligned.m8n8.x4.trans.shared.b16 {%0,%1,%2,%3}, [%4];"
                 : "=r"(r0), "=r"(r1), "=r"(r2), "=r"(r3) : "r"(a));
}
__device__ __forceinline__ void mma_fp16(float* d, const uint32_t* a,
                                         uint32_t b0, uint32_t b1) {
    asm volatile("mma.sync.aligned.m16n8k16.row.col.f32.f16.f16.f32 "
                 "{%0,%1,%2,%3}, {%4,%5,%6,%7}, {%8,%9}, {%0,%1,%2,%3};"
                 : "+f"(d[0]), "+f"(d[1]), "+f"(d[2]), "+f"(d[3])
                 : "r"(a[0]), "r"(a[1]), "r"(a[2]), "r"(a[3]),
                   "r"(b0), "r"(b1));
}
__device__ __forceinline__ float2 h2f2(uint32_t h) {
    __half2 v = *reinterpret_cast<__half2*>(&h);
    return __half22float2(v);
}

// ---------------------------------------------------------------------------
// prep: W1/W2 -> fp16 B-fragment images (R12-proven mapping).
// ---------------------------------------------------------------------------
__global__ void prep_kernel(const float* __restrict__ W1, const float* __restrict__ W2)
{
    int i = blockIdx.x * blockDim.x + threadIdx.x;
    if (i >= 12288) return;
    int lane = i & 31, p = (i >> 5) & 3, s = (i >> 7) & 3, wn = (i >> 9) & 3, kc = i >> 11;
    int g = lane >> 2, tq = lane & 3;
    int n0 = wn*64 + p*16 + g;
    int kk = s*16 + 2*tq;
    const float* W = (kc < 2) ? W1 : W2;
    int k0 = (kc < 2) ? kc*64 : (kc - 2)*64;

    __half2 w0 = __floats2half2_rn(W[(size_t)(k0+kk  )*256 + n0],   W[(size_t)(k0+kk+1)*256 + n0]);
    __half2 w1 = __floats2half2_rn(W[(size_t)(k0+kk+8)*256 + n0],   W[(size_t)(k0+kk+9)*256 + n0]);
    __half2 w2 = __floats2half2_rn(W[(size_t)(k0+kk  )*256 + n0+8], W[(size_t)(k0+kk+1)*256 + n0+8]);
    __half2 w3 = __floats2half2_rn(W[(size_t)(k0+kk+8)*256 + n0+8], W[(size_t)(k0+kk+9)*256 + n0+8]);
    uint4 o;
    o.x = *reinterpret_cast<uint32_t*>(&w0);
    o.y = *reinterpret_cast<uint32_t*>(&w1);
    o.z = *reinterpret_cast<uint32_t*>(&w2);
    o.w = *reinterpret_cast<uint32_t*>(&w3);
    g_Wf[i] = o;
}

// ---------------------------------------------------------------------------
// phi kernel (R16 body; src/isq now parameters so phi_k can launch alone
// and unblock kv while phi_q overlaps it on a forked stream).
// 64 tokens/CTA, 256 threads (8 warps, 2M x 4N), 2 CTAs/SM. grid 2048.
// ---------------------------------------------------------------------------
#define PHI_SMEM 37120

__global__ void __launch_bounds__(256, 2) phi_mma_kernel(
    const float* __restrict__ src,
    const float* __restrict__ b1, const float* __restrict__ b2, const int isq)
{
    extern __shared__ char smc[];
    __half* sAh = reinterpret_cast<__half*>(smc);
    float* sB1  = reinterpret_cast<float*>(smc + 33792);
    float* sB2  = reinterpret_cast<float*>(smc + 34816);
    float* sPrt = reinterpret_cast<float*>(smc + 35840);
    float* sInv = reinterpret_cast<float*>(smc + 36864);
    const uint32_t abase = smem_u32(smc);

    const int tid  = threadIdx.x;
    const int wid  = tid >> 5;
    const int lane = tid & 31;
    const int g    = lane >> 2;
    const int tq   = lane & 3;
    const int wm   = wid & 1;
    const int wn   = wid >> 1;

    const int tok0 = blockIdx.x * 64;

    {
        const float4* s4 = reinterpret_cast<const float4*>(src + (size_t)tok0 * DD);
        #pragma unroll
        for (int l = 0; l < 8; ++l) {
            int id  = tid + l * 256;
            int row = id >> 5, c4 = id & 31;
            float4 v = s4[row * 32 + c4];
            __half2* p = reinterpret_cast<__half2*>(sAh + row*136 + c4*4);
            p[0] = __floats2half2_rn(v.x, v.y);
            p[1] = __floats2half2_rn(v.z, v.w);
        }
    }
    sB1[tid] = b1[tid];
    sB2[tid] = b2[tid];
    __syncthreads();

    float acc[2][8][4];
    #pragma unroll
    for (int mt = 0; mt < 2; ++mt)
        #pragma unroll
        for (int nt = 0; nt < 8; ++nt)
            #pragma unroll
            for (int e = 0; e < 4; ++e) acc[mt][nt][e] = 0.f;

    const int amrow   = wm*32 + (lane & 15);
    const int acoladd = ((lane >> 4) << 3);
    const int wfbase = wn*512 + lane;

    uint4 bv[2][4];
    #pragma unroll
    for (int p = 0; p < 4; ++p) bv[0][p] = g_Wf[wfbase + p*32];

    #pragma unroll
    for (int kc = 0; kc < 6; ++kc) {
        if (kc == 2) {
            __syncthreads();
            #pragma unroll
            for (int mt = 0; mt < 2; ++mt)
                #pragma unroll
                for (int nt = 0; nt < 8; ++nt) {
                    const int col = wn*64 + nt*8 + tq*2;
                    #pragma unroll
                    for (int h = 0; h < 2; ++h) {
                        const int row = wm*32 + mt*16 + 8*h + g;
                        float x0 = acc[mt][nt][h*2]   + sB1[col];
                        float x1 = acc[mt][nt][h*2+1] + sB1[col+1];
                        float s0 = x0 / (1.f + __expf(-x0));
                        float s1 = x1 / (1.f + __expf(-x1));
                        *reinterpret_cast<__half2*>(sAh + row*264 + col) =
                            __floats2half2_rn(s0, s1);
                        acc[mt][nt][h*2] = 0.f;
                        acc[mt][nt][h*2+1] = 0.f;
                    }
                }
            __syncthreads();
        }

        #pragma unroll
        for (int s = 0; s < 4; ++s) {
            const int step = kc*4 + s;
            const int cur  = step & 1;

            if (step < 23) {
                const int ns = step + 1;
                const int nbase = (ns >> 2) * 2048 + ((ns & 3) * 128) + wfbase;
                #pragma unroll
                for (int p = 0; p < 4; ++p)
                    bv[cur ^ 1][p] = g_Wf[nbase + p*32];
            }

            const bool s1s = (kc < 2);
            const int astr = s1s ? 136 : 264;
            const int kbase = (s1s ? kc*64 : (kc - 2)*64) + s*16;
            uint32_t a[2][4];
            #pragma unroll
            for (int mt = 0; mt < 2; ++mt) {
                uint32_t ad = abase +
                    (uint32_t)(((amrow + mt*16) * astr) + kbase + acoladd) * 2u;
                ldsm_x4(a[mt][0], a[mt][1], a[mt][2], a[mt][3], ad);
            }

            #pragma unroll
            for (int p = 0; p < 4; ++p) {
                const uint4 b = bv[cur][p];
                mma_fp16(acc[0][2*p],   a[0], b.x, b.y);
                mma_fp16(acc[0][2*p+1], a[0], b.z, b.w);
                mma_fp16(acc[1][2*p],   a[1], b.x, b.y);
                mma_fp16(acc[1][2*p+1], a[1], b.z, b.w);
            }
        }
    }

    // ===== epilogue 2: p = elu(acc + b2)+1, row L2 norm =====
    float ss[2][2] = {};
    #pragma unroll
    for (int mt = 0; mt < 2; ++mt)
        #pragma unroll
        for (int nt = 0; nt < 8; ++nt) {
            const int col = wn*64 + nt*8 + tq*2;
            #pragma unroll
            for (int h = 0; h < 2; ++h)
                #pragma unroll
                for (int pr = 0; pr < 2; ++pr) {
                    float x = acc[mt][nt][h*2+pr] + sB2[col+pr];
                    float p = (x > 0.f) ? (x + 1.f) : __expf(x);
                    acc[mt][nt][h*2+pr] = p;
                    ss[mt][h] = fmaf(p, p, ss[mt][h]);
                }
        }
    #pragma unroll
    for (int m = 1; m <= 2; m <<= 1)
        #pragma unroll
        for (int mt = 0; mt < 2; ++mt)
            #pragma unroll
            for (int h = 0; h < 2; ++h)
                ss[mt][h] += __shfl_xor_sync(0xffffffffu, ss[mt][h], m);
    if (tq == 0) {
        #pragma unroll
        for (int mt = 0; mt < 2; ++mt)
            #pragma unroll
            for (int h = 0; h < 2; ++h)
                sPrt[wn*64 + wm*32 + mt*16 + 8*h + g] = ss[mt][h];
    }
    __syncthreads();
    if (tid < 64)
        sInv[tid] = 1.f / (sqrtf(sPrt[tid] + sPrt[64+tid] +
                                 sPrt[128+tid] + sPrt[192+tid]) + 1e-6f);
    __syncthreads();

    if (isq) {
        const int tb0 = (tok0 >> 4) + wm*2;
        #pragma unroll
        for (int mt = 0; mt < 2; ++mt) {
            const float inv0 = sInv[wm*32 + mt*16 + g];
            const float inv1 = sInv[wm*32 + mt*16 + 8 + g];
            const int tb = tb0 + mt;
            #pragma unroll
            for (int np = 0; np < 4; ++np) {
                const int ntE = 2*np, ntO = 2*np + 1;
                __half2 hx = __floats2half2_rn(acc[mt][ntE][0]*inv0, acc[mt][ntE][1]*inv0);
                __half2 hy = __floats2half2_rn(acc[mt][ntE][2]*inv1, acc[mt][ntE][3]*inv1);
                __half2 hz = __floats2half2_rn(acc[mt][ntO][0]*inv0, acc[mt][ntO][1]*inv0);
                __half2 hw = __floats2half2_rn(acc[mt][ntO][2]*inv1, acc[mt][ntO][3]*inv1);
                uint4 o;
                o.x = *reinterpret_cast<uint32_t*>(&hx);
                o.y = *reinterpret_cast<uint32_t*>(&hy);
                o.z = *reinterpret_cast<uint32_t*>(&hz);
                o.w = *reinterpret_cast<uint32_t*>(&hw);
                g_phiqf[((size_t)tb*16 + (wn*4 + np))*32 + lane] = o;
            }
        }
    } else {
        #pragma unroll
        for (int mt = 0; mt < 2; ++mt)
            #pragma unroll
            for (int h = 0; h < 2; ++h) {
                const int row = wm*32 + mt*16 + 8*h + g;
                const float inv = sInv[row];
                __half* dr = g_phi_k + (size_t)(tok0 + row) * FF;
                #pragma unroll
                for (int nt = 0; nt < 8; ++nt) {
                    const int col = wn*64 + nt*8 + tq*2;
                    *reinterpret_cast<__half2*>(dr + col) =
                        __floats2half2_rn(acc[mt][nt][h*2] * inv,
                                          acc[mt][nt][h*2+1] * inv);
                }
            }
    }
}

// ---------------------------------------------------------------------------
// kv kernel (unchanged): inline v fp32->fp16 staging, cp.async P, S=2.
// ---------------------------------------------------------------------------
#define KV_SMEM 34816

__global__ void __launch_bounds__(512, 2) kv_mma_kernel(const float* __restrict__ v)
{
    extern __shared__ char kvc[];
    const uint32_t sbase = smem_u32(kvc);

    const int hh = blockIdx.x;
    const int f0 = blockIdx.y * 128;
    const int ks = blockIdx.z;
    const int tid  = threadIdx.x;
    const int lane = tid & 31;
    const int wid  = tid >> 5;
    const int g  = lane >> 2;
    const int tq = lane & 3;
    const int wm = wid & 3;
    const int wn = wid >> 2;

    const __half* pbase = g_phi_k + ((size_t)hh * NSEQ + (size_t)ks * 1024) * FF + f0;
    const float*  vbase = v       + ((size_t)hh * NSEQ + (size_t)ks * 1024) * DD;

    const int vrow = tid >> 4;
    const int vseg = tid & 15;
    const uint32_t vsts_off = (uint32_t)(vrow*272 + vseg*16);

    auto issueP = [&](int b, int slot) {
        uint32_t base = sbase + (uint32_t)slot * 17408u;
        cp_async16(base + vrow*272 + vseg*16,
                   pbase + (size_t)(b*32 + vrow)*FF + vseg*8);
        CP_COMMIT();
    };
    auto ldgV = [&](int b, float4& v0, float4& v1) {
        const float4* p = reinterpret_cast<const float4*>(
            vbase + (size_t)(b*32 + vrow)*DD + vseg*8);
        v0 = p[0]; v1 = p[1];
    };

    float4 va0, va1;
    ldgV(0, va0, va1);
    issueP(0, 0);

    float acc[2][4][4];
    #pragma unroll
    for (int mt = 0; mt < 2; ++mt)
        #pragma unroll
        for (int nt = 0; nt < 4; ++nt)
            #pragma unroll
            for (int e = 0; e < 4; ++e) acc[mt][nt][e] = 0.f;
    float ksacc = 0.f;

    const int aseq = ((lane >> 4) << 3) + (lane & 7);
    const int afc  = wm*32 + ((lane >> 3) & 1) * 8;
    const int bseq = ((lane >> 3) & 1) * 8 + (lane & 7);
    const int bdc  = wn*32 + ((lane >> 4) << 3);

    for (int b = 0; b < 32; ++b) {
        {
            __half2 h0 = __floats2half2_rn(va0.x, va0.y);
            __half2 h1 = __floats2half2_rn(va0.z, va0.w);
            __half2 h2 = __floats2half2_rn(va1.x, va1.y);
            __half2 h3 = __floats2half2_rn(va1.z, va1.w);
            uint32_t addr = sbase + (uint32_t)(b & 1)*17408u + 8704u + vsts_off;
            asm volatile("st.shared.v4.b32 [%0], {%1,%2,%3,%4};" :: "r"(addr),
                "r"(*reinterpret_cast<uint32_t*>(&h0)),
                "r"(*reinterpret_cast<uint32_t*>(&h1)),
                "r"(*reinterpret_cast<uint32_t*>(&h2)),
                "r"(*reinterpret_cast<uint32_t*>(&h3)) : "memory");
        }
        CP_WAIT0();
        __syncthreads();
        if (b < 31) { issueP(b + 1, (b + 1) & 1); ldgV(b + 1, va0, va1); }

        const uint32_t pb = sbase + (uint32_t)(b & 1) * 17408u;
        const uint32_t vb = pb + 8704u;
        const __half* sP = reinterpret_cast<const __half*>(kvc + (b & 1) * 17408);

        if (tid < 128) {
            #pragma unroll
            for (int r = 0; r < 32; ++r)
                ksacc += __half2float(sP[r*136 + tid]);
        }

        uint32_t a[2][2][4];
        #pragma unroll
        for (int s = 0; s < 2; ++s)
            #pragma unroll
            for (int mt = 0; mt < 2; ++mt) {
                uint32_t ad = pb + (uint32_t)(((s*16 + aseq) * 136) + afc + mt*16) * 2u;
                ldsm_x4t(a[mt][s][0], a[mt][s][1], a[mt][s][2], a[mt][s][3], ad);
            }
        #pragma unroll
        for (int s = 0; s < 2; ++s)
            #pragma unroll
            for (int p = 0; p < 2; ++p) {
                uint32_t b0, b1v, b2, b3;
                uint32_t bd = vb + (uint32_t)(((s*16 + bseq) * 136) + bdc + p*16) * 2u;
                ldsm_x4t(b0, b1v, b2, b3, bd);
                mma_fp16(acc[0][2*p],   a[0][s], b0, b1v);
                mma_fp16(acc[0][2*p+1], a[0][s], b2, b3);
                mma_fp16(acc[1][2*p],   a[1][s], b0, b1v);
                mma_fp16(acc[1][2*p+1], a[1][s], b2, b3);
            }
    }

    float* outp = g_kvp + ((size_t)ks * BH + hh) * FF * DD;
    #pragma unroll
    for (int mt = 0; mt < 2; ++mt)
        #pragma unroll
        for (int h = 0; h < 2; ++h) {
            const int f = f0 + wm*32 + mt*16 + 8*h + g;
            #pragma unroll
            for (int nt = 0; nt < 4; ++nt) {
                const int d = wn*32 + nt*8 + tq*2;
                *reinterpret_cast<float2*>(outp + (size_t)f * DD + d) =
                    make_float2(acc[mt][nt][h*2], acc[mt][nt][h*2+1]);
            }
        }
    if (tid < 128)
        g_ksp[((size_t)ks * BH + hh) * FF + f0 + tid] = ksacc;
}

// ---------------------------------------------------------------------------
// reduce kernel (unchanged)
// ---------------------------------------------------------------------------
__global__ void reduce_kernel()
{
    const int NKV4 = BH * FF * DD / 4;
    const int NKS  = BH * FF;
    int i = blockIdx.x * blockDim.x + threadIdx.x;
    if (i < NKV4) {
        float4 s = make_float4(0.f, 0.f, 0.f, 0.f);
        #pragma unroll
        for (int p = 0; p < KSPLIT; ++p) {
            float4 t = reinterpret_cast<const float4*>(g_kvp)[(size_t)p * NKV4 + i];
            s.x += t.x; s.y += t.y; s.z += t.z; s.w += t.w;
        }
        __half2* o = reinterpret_cast<__half2*>(g_kvh + (size_t)i*4);
        o[0] = __floats2half2_rn(s.x, s.y);
        o[1] = __floats2half2_rn(s.z, s.w);
    } else {
        int j = i - NKV4;
        if (j < NKS) {
            float s = 0.f;
            #pragma unroll
            for (int p = 0; p < KSPLIT; ++p) s += g_ksp[(size_t)p * NKS + j];
            g_ksum[j] = s;
        }
    }
}

// ---------------------------------------------------------------------------
// qkv kernel (unchanged from R16).
// ---------------------------------------------------------------------------
#define QSLOT 8704u
#define QKV_SMEM 17408

__global__ void __launch_bounds__(512) qkv_mma_kernel(float* __restrict__ out)
{
    extern __shared__ char qc[];
    __shared__ float sKs[2][32];
    __shared__ float sDen[256];
    const uint32_t sbase = smem_u32(qc);

    const int hh = blockIdx.x;
    const int m0 = blockIdx.y * 256;
    const int tid  = threadIdx.x;
    const int lane = tid & 31;
    const int wid  = tid >> 5;
    const int g  = lane >> 2;
    const int tq = lane & 3;
    const int wm = wid & 7;
    const int wn = wid >> 3;

    const __half* bgb = g_kvh + (size_t)hh * FF * DD;
    const size_t fbase = ((size_t)hh*256 + (m0 >> 4) + wm*2) * 16 * 32 + lane;

    auto issueB = [&](int kc, int slot) {
        uint32_t base = sbase + (uint32_t)slot * QSLOT;
        int row = tid >> 4, seg = tid & 15;
        cp_async16(base + row*272 + seg*16,
                   bgb + (size_t)(kc*32 + row)*DD + seg*8);
        CP_COMMIT();
    };

    issueB(0, 0);
    if (tid < 32) sKs[0][tid] = g_ksum[(size_t)hh * FF + tid];

    uint4 fa[2][4];
    #pragma unroll
    for (int mt = 0; mt < 2; ++mt)
        #pragma unroll
        for (int s = 0; s < 2; ++s)
            fa[0][mt*2+s] = g_phiqf[fbase + ((size_t)mt*16 + s)*32];

    float acc[2][8][4];
    #pragma unroll
    for (int mt = 0; mt < 2; ++mt)
        #pragma unroll
        for (int nt = 0; nt < 8; ++nt)
            #pragma unroll
            for (int e = 0; e < 4; ++e) acc[mt][nt][e] = 0.f;
    float den4[2][2] = {};

    const int bseq = ((lane >> 3) & 1) * 8 + (lane & 7);
    const int bdc  = wn*64 + ((lane >> 4) << 3);

    for (int kc = 0; kc < 8; ++kc) {
        const int cur = kc & 1;
        if (kc < 7) {
            #pragma unroll
            for (int mt = 0; mt < 2; ++mt)
                #pragma unroll
                for (int s = 0; s < 2; ++s)
                    fa[cur ^ 1][mt*2+s] =
                        g_phiqf[fbase + ((size_t)mt*16 + (kc+1)*2 + s)*32];
        }

        CP_WAIT0();
        __syncthreads();
        if (kc < 7) {
            issueB(kc + 1, (kc + 1) & 1);
            if (tid < 32)
                sKs[(kc+1) & 1][tid] = g_ksum[(size_t)hh * FF + (kc+1)*32 + tid];
        }

        const uint32_t bb = sbase + (uint32_t)cur * QSLOT;
        const float* ks = sKs[cur];

        if (wn == 0) {
            #pragma unroll
            for (int mt = 0; mt < 2; ++mt)
                #pragma unroll
                for (int s = 0; s < 2; ++s) {
                    const uint4 f = fa[cur][mt*2+s];
                    const int k0 = s*16 + 2*tq;
                    float2 xv = h2f2(f.x), yv = h2f2(f.y);
                    float2 zv = h2f2(f.z), wv = h2f2(f.w);
                    den4[mt][0] = fmaf(xv.x, ks[k0],   den4[mt][0]);
                    den4[mt][0] = fmaf(xv.y, ks[k0+1], den4[mt][0]);
                    den4[mt][0] = fmaf(zv.x, ks[k0+8], den4[mt][0]);
                    den4[mt][0] = fmaf(zv.y, ks[k0+9], den4[mt][0]);
                    den4[mt][1] = fmaf(yv.x, ks[k0],   den4[mt][1]);
                    den4[mt][1] = fmaf(yv.y, ks[k0+1], den4[mt][1]);
                    den4[mt][1] = fmaf(wv.x, ks[k0+8], den4[mt][1]);
                    den4[mt][1] = fmaf(wv.y, ks[k0+9], den4[mt][1]);
                }
        }

        #pragma unroll
        for (int s = 0; s < 2; ++s) {
            const uint32_t* a0 = reinterpret_cast<const uint32_t*>(&fa[cur][s]);
            const uint32_t* a1 = reinterpret_cast<const uint32_t*>(&fa[cur][2+s]);
            #pragma unroll
            for (int p = 0; p < 4; ++p) {
                uint32_t b0, b1v, b2, b3;
                uint32_t bd = bb + (uint32_t)(((s*16 + bseq) * 136) + bdc + p*16) * 2u;
                ldsm_x4t(b0, b1v, b2, b3, bd);
                mma_fp16(acc[0][2*p],   a0, b0, b1v);
                mma_fp16(acc[0][2*p+1], a0, b2, b3);
                mma_fp16(acc[1][2*p],   a1, b0, b1v);
                mma_fp16(acc[1][2*p+1], a1, b2, b3);
            }
        }
    }

    #pragma unroll
    for (int m = 1; m <= 2; m <<= 1)
        #pragma unroll
        for (int mt = 0; mt < 2; ++mt)
            #pragma unroll
            for (int h = 0; h < 2; ++h)
                den4[mt][h] += __shfl_xor_sync(0xffffffffu, den4[mt][h], m);
    if (wn == 0 && tq == 0) {
        #pragma unroll
        for (int mt = 0; mt < 2; ++mt) {
            sDen[wm*32 + mt*16 + g]     = den4[mt][0];
            sDen[wm*32 + mt*16 + 8 + g] = den4[mt][1];
        }
    }
    __syncthreads();

    float* op = out + ((size_t)hh * NSEQ + m0) * DD;
    #pragma unroll
    for (int mt = 0; mt < 2; ++mt)
        #pragma unroll
        for (int h = 0; h < 2; ++h) {
            const int row = wm*32 + mt*16 + 8*h + g;
            const float invd = 1.f / fmaxf(sDen[row], 1e-6f);
            #pragma unroll
            for (int nt = 0; nt < 8; ++nt) {
                const int d = wn*64 + nt*8 + tq*2;
                *reinterpret_cast<float2*>(op + (size_t)row * DD + d) =
                    make_float2(acc[mt][nt][h*2] * invd, acc[mt][nt][h*2+1] * invd);
            }
        }
}

// ---------------------------------------------------------------------------
// launch: fork kv onto a side stream so it overlaps phi_q.
//   s0: prep -> phi_k -> [e1] -> phi_q -> (wait e2) -> reduce -> qkv
//   s1: (wait e1) -> kv -> [e2]
// Stream/event creation is host-side (no device alloc); kernel_launch runs
// only for the correctness call + the capture call, so handles leak boundedly.
// ---------------------------------------------------------------------------
extern "C" void kernel_launch(void* const* d_in, const int* in_sizes, int n_in,
                              void* d_out, int out_size)
{
    (void)in_sizes; (void)n_in; (void)out_size;
    const float* q  = (const float*)d_in[0];
    const float* k  = (const float*)d_in[1];
    const float* v  = (const float*)d_in[2];
    const float* W1 = (const float*)d_in[3];
    const float* b1 = (const float*)d_in[4];
    const float* W2 = (const float*)d_in[5];
    const float* b2 = (const float*)d_in[6];
    float* out = (float*)d_out;

    cudaFuncSetAttribute(phi_mma_kernel, cudaFuncAttributeMaxDynamicSharedMemorySize, PHI_SMEM);
    cudaFuncSetAttribute(kv_mma_kernel,  cudaFuncAttributeMaxDynamicSharedMemorySize, KV_SMEM);
    cudaFuncSetAttribute(qkv_mma_kernel, cudaFuncAttributeMaxDynamicSharedMemorySize, QKV_SMEM);

    cudaStream_t s1;
    cudaEvent_t e1, e2;
    cudaStreamCreateWithFlags(&s1, cudaStreamNonBlocking);
    cudaEventCreateWithFlags(&e1, cudaEventDisableTiming);
    cudaEventCreateWithFlags(&e2, cudaEventDisableTiming);

    prep_kernel<<<48, 256>>>(W1, W2);
    phi_mma_kernel<<<2048, 256, PHI_SMEM>>>(k, b1, b2, 0);   // phi_k
    cudaEventRecord(e1, 0);
    cudaStreamWaitEvent(s1, e1, 0);
    kv_mma_kernel<<<dim3(32, 2, KSPLIT), 512, KV_SMEM, s1>>>(v);
    cudaEventRecord(e2, s1);
    phi_mma_kernel<<<2048, 256, PHI_SMEM>>>(q, b1, b2, 1);   // phi_q (overlaps kv)
    cudaStreamWaitEvent(0, e2, 0);
    {
        const int total = BH*FF*DD/4 + BH*FF;
        reduce_kernel<<<(total + 255) / 256, 256>>>();
    }
    qkv_mma_kernel<<<dim3(32, 16), 512, QKV_SMEM>>>(out);
}